// round 13
// baseline (speedup 1.0000x reference)
#include <cuda_runtime.h>
#include <cuda_fp16.h>
#include <cstdint>

#define D_DIM 256
#define N_TOK 32768
#define N_CODE 2048

// ---------------- scratch (static device globals) ---------------------------
__device__ __half g_ehi[N_CODE * D_DIM];  // E hi split, B-fragment order
__device__ __half g_elo[N_CODE * D_DIM];  // E lo split
__device__ float  g_embed[N_CODE * D_DIM];// E row-major (gather)
__device__ float  g_esq[N_CODE];          // ||e||^2
__device__ unsigned long long g_key[N_TOK]; // packed (mono(dist)<<32 | code)

// ---------------- helpers ----------------------------------------------------
__device__ __forceinline__ uint32_t smem_u32(const void* p) {
    uint32_t a;
    asm("{ .reg .u64 t; cvta.to.shared.u64 t, %1; cvt.u32.u64 %0, t; }"
        : "=r"(a) : "l"(p));
    return a;
}
__device__ __forceinline__ uint32_t pack2(__half a, __half b) {
    __half2 h2 = __halves2half2(a, b);
    return *reinterpret_cast<uint32_t*>(&h2);
}
// monotone float->uint mapping (preserves total order)
__device__ __forceinline__ uint32_t fmono(float f) {
    uint32_t b = __float_as_uint(f);
    return b ^ ((b & 0x80000000u) ? 0xFFFFFFFFu : 0x80000000u);
}

#define MBAR_INIT(a, c) asm volatile("mbarrier.init.shared.b64 [%0], %1;" :: "r"(a), "r"((uint32_t)(c)) : "memory")
#define MBAR_EXPECT_TX(a, b) asm volatile("mbarrier.arrive.expect_tx.shared.b64 _, [%0], %1;" :: "r"(a), "r"((uint32_t)(b)) : "memory")
#define MBAR_ARRIVE(a)  asm volatile("mbarrier.arrive.shared.b64 _, [%0];" :: "r"(a) : "memory")

#define MBAR_WAIT(mbar, parity) do {                                          \
    uint32_t _m = (mbar), _ph = (parity), _done;                              \
    asm volatile("{ .reg .pred p; mbarrier.try_wait.parity.acquire.cta.shared::cta.b64 p, [%1], %2; selp.b32 %0, 1, 0, p; }" \
                 : "=r"(_done) : "r"(_m), "r"(_ph) : "memory");               \
    if (!_done) {                                                             \
        asm volatile("{ .reg .pred P1; WL_%=: mbarrier.try_wait.parity.acquire.cta.shared::cta.b64 P1, [%0], %1, 0x989680; @P1 bra.uni WD_%=; bra.uni WL_%=; WD_%=: }" \
                     :: "r"(_m), "r"(_ph) : "memory");                        \
    }                                                                         \
} while (0)

#define BULK_G2S(dst, src, bytes, mbar)                                       \
    asm volatile("cp.async.bulk.shared::cluster.global.mbarrier::complete_tx::bytes [%0], [%1], %2, [%3];" \
                 :: "r"(dst), "l"(src), "r"((uint32_t)(bytes)), "r"(mbar) : "memory")

// mma.sync m16n8k16 fp16 -> fp32 accumulate
__device__ __forceinline__ void mma_f16(float* d, const uint32_t* a, const uint32_t* b) {
    asm("mma.sync.aligned.m16n8k16.row.col.f32.f16.f16.f32 "
        "{%0,%1,%2,%3}, {%4,%5,%6,%7}, {%8,%9}, {%0,%1,%2,%3};"
        : "+f"(d[0]), "+f"(d[1]), "+f"(d[2]), "+f"(d[3])
        : "r"(a[0]), "r"(a[1]), "r"(a[2]), "r"(a[3]), "r"(b[0]), "r"(b[1]));
}

// ---------------------------------------------------------------------------
// prep (E only now): embed = embed_sum / max(u,eps); row-major copy, esq,
// fp16 split in B-fragment order. 1024 blocks x 256 threads (2 codes/block).
// Also initializes g_key (32 keys per block).
// ---------------------------------------------------------------------------
__global__ void __launch_bounds__(256) prep_e_kernel(const float* __restrict__ embed_sum,
                                                     const float* __restrict__ usage) {
    int t = threadIdx.x;
    int k = blockIdx.x * 2 + (t >> 7);
    int tl = t & 127;
    __shared__ float wsum[8];

    if (t < 32) g_key[blockIdx.x * 32 + t] = 0xFFFFFFFFFFFFFFFFull;

    float u = fmaxf(usage[k], 1e-5f);
    float2 vv = ((const float2*)embed_sum)[k * 128 + tl];
    float v0 = vv.x / u, v1 = vv.y / u;
    ((float2*)g_embed)[k * 128 + tl] = make_float2(v0, v1);

    __half h0 = __float2half_rn(v0);
    __half l0 = __float2half_rn(v0 - __half2float(h0));
    __half h1 = __float2half_rn(v1);
    __half l1 = __float2half_rn(v1 - __half2float(h1));

    int d = 2 * tl;
    int pass = k >> 7, n_in = k & 127;
    int n_tile = n_in >> 3, ncol = n_in & 7;
    int ch = d >> 6, kk = d & 63, ks = kk >> 4, kc = kk & 15;
    int lane = ncol * 4 + ((kc >> 1) & 3);
    int reg = kc >> 3;
    int hbase = (pass * 4 + ch) * 8192 + ((ks * 16 + n_tile) * 32 + lane) * 4 + reg * 2;
    ((uint32_t*)g_ehi)[hbase >> 1] = pack2(h0, h1);
    ((uint32_t*)g_elo)[hbase >> 1] = pack2(l0, l1);

    float val = v0 * v0 + v1 * v1;
    #pragma unroll
    for (int off = 16; off > 0; off >>= 1)
        val += __shfl_down_sync(0xffffffffu, val, off);
    if ((t & 31) == 0) wsum[t >> 5] = val;
    __syncthreads();
    if (tl == 0) {
        int w0 = (t >> 7) * 4;
        g_esq[k] = wsum[w0] + wsum[w0 + 1] + wsum[w0 + 2] + wsum[w0 + 3];
    }
}

// ---------------------------------------------------------------------------
// Fused fp16x2 mma.sync GEMM + argmin, with IN-KERNEL X split.
// Grid: 1024 CTAs = 256 m-tiles x 4 quarters. 288 threads = 8 compute + 1 prod.
// A region (128 KB): [half0: tokens 0-63][half1: tokens 64-127]; each half =
//   4 chunks x (hi 8 KB | lo 8 KB). Raw X lands: tokens 0-63 -> A half1 (temp),
//   tokens 64-127 -> B stages 0+1 (temp). Conversions (disjoint src/dst):
//   conv1: A-upper raw -> A-lower fragments; conv2: B raw -> A-upper fragments.
// B ring starts at stage 2 (free at t=0); stages 0/1 gated on XE0.
// ---------------------------------------------------------------------------
#define SMEM_TOTAL 232448
#define A_OFF 3072
#define B_OFF 134144

__device__ __forceinline__ void conv_block(char* smem, const char* src_base,
                                           int tok_base, int ct) {
    int tok_l = ct >> 2;        // 0..63
    int cseg = ct & 3;          // chunk
    const float4* src = (const float4*)(src_base + tok_l * 1024 + cseg * 256);
    int tok = tok_base + tok_l;
    int m_tile = tok >> 4;
    int h = m_tile >> 2, mtl = m_tile & 3, r = tok & 15;
    char* dst_hi = smem + A_OFF + h * 65536 + cseg * 16384;
    char* dst_lo = dst_hi + 8192;
    #pragma unroll
    for (int i = 0; i < 16; ++i) {
        float4 v = src[i];
        float xv[4] = {v.x, v.y, v.z, v.w};
        #pragma unroll
        for (int j = 0; j < 4; j += 2) {
            __half ha = __float2half_rn(xv[j]);
            __half la = __float2half_rn(xv[j] - __half2float(ha));
            __half hb = __float2half_rn(xv[j + 1]);
            __half lb = __float2half_rn(xv[j + 1] - __half2float(hb));
            int kk = i * 4 + j;
            int ks = kk >> 4, kc = kk & 15;
            int lane = (r & 7) * 4 + ((kc >> 1) & 3);
            int reg = (r >> 3) | ((kc >> 3) << 1);
            int hoff = (((ks * 4 + mtl) * 32 + lane) * 8 + reg * 2) * 2;
            *(uint32_t*)(dst_hi + hoff) = pack2(ha, hb);
            *(uint32_t*)(dst_lo + hoff) = pack2(la, lb);
        }
    }
}

__global__ void __launch_bounds__(288, 1) argmin_mma_kernel(const float* __restrict__ X) {
    extern __shared__ __align__(1024) char smem[];
    uint32_t sb = smem_u32(smem);
    int tid = threadIdx.x, lane = tid & 31, wid = tid >> 5;
    int mtile = blockIdx.x >> 2, q = blockIdx.x & 3;

    const uint32_t XFA   = sb + 0;
    const uint32_t FB[3] = {sb + 8,  sb + 16, sb + 24};
    const uint32_t EB[3] = {sb + 32, sb + 40, sb + 48};
    const uint32_t XFB   = sb + 56;
    const uint32_t XE0   = sb + 64;
    float* esq_s = (float*)(smem + 1024);   // [512] quarter esq

    if (tid == 0) {
        MBAR_INIT(XFA, 1); MBAR_INIT(XFB, 1); MBAR_INIT(XE0, 1);
        #pragma unroll
        for (int s = 0; s < 3; ++s) { MBAR_INIT(FB[s], 1); MBAR_INIT(EB[s], 8); }
    }
    for (int i = tid; i < 512; i += 288) esq_s[i] = g_esq[q * 512 + i];
    __syncthreads();

    int row0 = mtile * 128;

    if (wid == 8) {
        // ---------------- dedicated producer warp ---------------------------
        if (lane == 0) {
            const float* Xg = X + (size_t)mtile * 32768;   // m-tile, 128 KB
            // raw X: tokens 0-63 -> A upper half (temp); 64-127 -> B stages 0+1
            MBAR_EXPECT_TX(XFA, 65536);
            BULK_G2S(sb + A_OFF + 65536, Xg, 65536, XFA);
            MBAR_EXPECT_TX(XFB, 65536);
            BULK_G2S(sb + B_OFF, Xg + 16384, 65536, XFB);

            // B tiles: stage mapping s = (g+2)%3 (stage 2 first - free at t=0)
            #pragma unroll 1
            for (int g = 0; g < 16; ++g) {
                int s = (g + 2) % 3;
                int u = g / 3;
                if (g == 1) MBAR_WAIT(XE0, 0);          // raw X area freed
                if (u >= 1) MBAR_WAIT(EB[s], (u - 1) & 1);
                int pass = g >> 2, ch = g & 3;
                uint32_t st = sb + B_OFF + s * 32768;
                MBAR_EXPECT_TX(FB[s], 32768);
                BULK_G2S(st,         &g_ehi[((q * 4 + pass) * 4 + ch) * 8192], 16384, FB[s]);
                BULK_G2S(st + 16384, &g_elo[((q * 4 + pass) * 4 + ch) * 8192], 16384, FB[s]);
            }
        }
    } else {
        // ---------------- 8 compute warps (tid 0..255) ------------------------
        int warp_m = wid & 3, warp_n = wid >> 2;
        int t4 = lane & 3, g4 = lane >> 2;

        // ---- in-kernel X split prologue ----
        MBAR_WAIT(XFA, 0);
        conv_block(smem, smem + A_OFF + 65536, 0, tid);      // tokens 0-63 -> A lower
        asm volatile("bar.sync 1, 256;" ::: "memory");
        MBAR_WAIT(XFB, 0);
        conv_block(smem, smem + B_OFF, 64, tid);             // tokens 64-127 -> A upper
        asm volatile("bar.sync 1, 256;" ::: "memory");
        if (tid == 0) MBAR_ARRIVE(XE0);                      // B stages 0/1 free

        float best[2][2];
        int bestI[2][2];
        #pragma unroll
        for (int a = 0; a < 2; ++a)
            #pragma unroll
            for (int b = 0; b < 2; ++b) { best[a][b] = 3.4e38f; bestI[a][b] = 0; }

        int h_half = warp_m >> 1;                 // token half for this warp
        int mtl2 = (warp_m & 1) * 2;              // mt_local base

        #pragma unroll 1
        for (int pass = 0; pass < 4; ++pass) {
            float acc[2][8][4];
            #pragma unroll
            for (int mt = 0; mt < 2; ++mt)
                #pragma unroll
                for (int nt = 0; nt < 8; ++nt)
                    #pragma unroll
                    for (int j = 0; j < 4; ++j) acc[mt][nt][j] = 0.f;

            #pragma unroll 1
            for (int ch = 0; ch < 4; ++ch) {
                int g = pass * 4 + ch;
                int s = (g + 2) % 3;
                MBAR_WAIT(FB[s], (g / 3) & 1);

                const char* Abase = smem + A_OFF + h_half * 65536 + ch * 16384;
                const char* Bh = smem + B_OFF + s * 32768;
                const char* Bl = Bh + 16384;

                #pragma unroll
                for (int ks = 0; ks < 4; ++ks) {
                    uint32_t ah[2][4], al[2][4];
                    #pragma unroll
                    for (int mt = 0; mt < 2; ++mt) {
                        int off = ((ks * 4 + mtl2 + mt) * 32 + lane) * 16;
                        *(uint4*)ah[mt] = *(const uint4*)(Abase + off);
                        *(uint4*)al[mt] = *(const uint4*)(Abase + 8192 + off);
                    }
                    uint32_t bh[8][2], bl[8][2];
                    #pragma unroll
                    for (int nt = 0; nt < 8; ++nt) {
                        int off = ((ks * 16 + warp_n * 8 + nt) * 32 + lane) * 8;
                        *(uint2*)bh[nt] = *(const uint2*)(Bh + off);
                        *(uint2*)bl[nt] = *(const uint2*)(Bl + off);
                    }
                    // term-ordered: hi*hi, hi*lo, lo*hi
                    #pragma unroll
                    for (int mt = 0; mt < 2; ++mt)
                        #pragma unroll
                        for (int nt = 0; nt < 8; ++nt)
                            mma_f16(acc[mt][nt], ah[mt], bh[nt]);
                    #pragma unroll
                    for (int mt = 0; mt < 2; ++mt)
                        #pragma unroll
                        for (int nt = 0; nt < 8; ++nt)
                            mma_f16(acc[mt][nt], ah[mt], bl[nt]);
                    #pragma unroll
                    for (int mt = 0; mt < 2; ++mt)
                        #pragma unroll
                        for (int nt = 0; nt < 8; ++nt)
                            mma_f16(acc[mt][nt], al[mt], bh[nt]);
                }
                if (lane == 0) MBAR_ARRIVE(EB[s]);
            }

            // fold pass into running argmin: dist = esq - 2*dot
            #pragma unroll
            for (int nt = 0; nt < 8; ++nt) {
                int clocal = pass * 128 + warp_n * 64 + nt * 8 + 2 * t4;
                float e0 = esq_s[clocal], e1 = esq_s[clocal + 1];
                int cbase = q * 512 + clocal;
                #pragma unroll
                for (int mt = 0; mt < 2; ++mt) {
                    float d0v = fmaf(-2.f, acc[mt][nt][0], e0);
                    if (d0v < best[mt][0]) { best[mt][0] = d0v; bestI[mt][0] = cbase; }
                    float d1v = fmaf(-2.f, acc[mt][nt][1], e1);
                    if (d1v < best[mt][0]) { best[mt][0] = d1v; bestI[mt][0] = cbase + 1; }
                    float d2v = fmaf(-2.f, acc[mt][nt][2], e0);
                    if (d2v < best[mt][1]) { best[mt][1] = d2v; bestI[mt][1] = cbase; }
                    float d3v = fmaf(-2.f, acc[mt][nt][3], e1);
                    if (d3v < best[mt][1]) { best[mt][1] = d3v; bestI[mt][1] = cbase + 1; }
                }
            }
        }

        // width-4 shuffle reduce, then global atomic merge
        #pragma unroll
        for (int mt = 0; mt < 2; ++mt)
            #pragma unroll
            for (int h = 0; h < 2; ++h) {
                float b = best[mt][h];
                int bi = bestI[mt][h];
                #pragma unroll
                for (int off = 2; off > 0; off >>= 1) {
                    float ob = __shfl_down_sync(0xffffffffu, b, off, 4);
                    int obi = __shfl_down_sync(0xffffffffu, bi, off, 4);
                    if (ob < b || (ob == b && obi < bi)) { b = ob; bi = obi; }
                }
                if (t4 == 0) {
                    int tok = row0 + warp_m * 32 + mt * 16 + g4 + 8 * h;
                    unsigned long long key =
                        ((unsigned long long)fmono(b) << 32) | (uint32_t)bi;
                    atomicMin(&g_key[tok], key);
                }
            }
    }
}

// ---------------------------------------------------------------------------
// gather: one thread per (token, float4 chunk). 8192 CTAs x 256 threads.
// ---------------------------------------------------------------------------
__global__ void __launch_bounds__(256) gather_kernel(float* __restrict__ out, int N) {
    int i = blockIdx.x * 256 + threadIdx.x;     // [0, N*64)
    int tok = i >> 6, c4 = i & 63;
    int idx = (int)(g_key[tok] & 0xFFFFFFFFull);
    float4 v = ((const float4*)g_embed)[(size_t)idx * 64 + c4];
    ((float4*)out)[i] = v;
    if (c4 == 0) out[(size_t)N * D_DIM + tok] = (float)idx;
}

// ---------------------------------------------------------------------------
extern "C" void kernel_launch(void* const* d_in, const int* in_sizes, int n_in,
                              void* d_out, int out_size) {
    const float* X  = (const float*)d_in[0];
    const float* ES = (const float*)d_in[1];
    const float* U  = (const float*)d_in[2];
    float* out = (float*)d_out;
    (void)n_in; (void)out_size;
    int N = in_sizes[0] / D_DIM;   // 32768

    cudaFuncSetAttribute(argmin_mma_kernel,
                         cudaFuncAttributeMaxDynamicSharedMemorySize, SMEM_TOTAL);

    prep_e_kernel<<<N_CODE / 2, 256>>>(ES, U);
    argmin_mma_kernel<<<(N / 128) * 4, 288, SMEM_TOTAL>>>(X);
    gather_kernel<<<(N * 64) / 256, 256>>>(out, N);
}

// round 14
// speedup vs baseline: 1.2859x; 1.2859x over previous
#include <cuda_runtime.h>
#include <cuda_fp16.h>
#include <cstdint>

#define D_DIM 256
#define N_TOK 32768
#define N_CODE 2048

// ---------------- scratch (static device globals) ---------------------------
__device__ __half g_xhi[N_TOK * D_DIM];   // X hi split, m16n8k16 A-fragment order
__device__ __half g_xlo[N_TOK * D_DIM];   // X lo split
__device__ __half g_ehi[N_CODE * D_DIM];  // E hi split, paired B-fragment order
__device__ __half g_elo[N_CODE * D_DIM];  // E lo split
__device__ float  g_embed[N_CODE * D_DIM];// E row-major (gather)
__device__ float  g_esq[N_CODE];          // ||e||^2
__device__ unsigned long long g_key[N_TOK]; // packed (mono(dist)<<32 | code)

// ---------------- helpers ----------------------------------------------------
__device__ __forceinline__ uint32_t smem_u32(const void* p) {
    uint32_t a;
    asm("{ .reg .u64 t; cvta.to.shared.u64 t, %1; cvt.u32.u64 %0, t; }"
        : "=r"(a) : "l"(p));
    return a;
}
__device__ __forceinline__ uint32_t pack2(__half a, __half b) {
    __half2 h2 = __halves2half2(a, b);
    return *reinterpret_cast<uint32_t*>(&h2);
}
// monotone float->uint mapping (preserves total order)
__device__ __forceinline__ uint32_t fmono(float f) {
    uint32_t b = __float_as_uint(f);
    return b ^ ((b & 0x80000000u) ? 0xFFFFFFFFu : 0x80000000u);
}

#define MBAR_INIT(a, c) asm volatile("mbarrier.init.shared.b64 [%0], %1;" :: "r"(a), "r"((uint32_t)(c)) : "memory")
#define MBAR_EXPECT_TX(a, b) asm volatile("mbarrier.arrive.expect_tx.shared.b64 _, [%0], %1;" :: "r"(a), "r"((uint32_t)(b)) : "memory")
#define MBAR_ARRIVE(a)  asm volatile("mbarrier.arrive.shared.b64 _, [%0];" :: "r"(a) : "memory")

#define MBAR_WAIT(mbar, parity) do {                                          \
    uint32_t _m = (mbar), _ph = (parity), _done;                              \
    asm volatile("{ .reg .pred p; mbarrier.try_wait.parity.acquire.cta.shared::cta.b64 p, [%1], %2; selp.b32 %0, 1, 0, p; }" \
                 : "=r"(_done) : "r"(_m), "r"(_ph) : "memory");               \
    if (!_done) {                                                             \
        asm volatile("{ .reg .pred P1; WL_%=: mbarrier.try_wait.parity.acquire.cta.shared::cta.b64 P1, [%0], %1, 0x989680; @P1 bra.uni WD_%=; bra.uni WL_%=; WD_%=: }" \
                     :: "r"(_m), "r"(_ph) : "memory");                        \
    }                                                                         \
} while (0)

#define BULK_G2S(dst, src, bytes, mbar)                                       \
    asm volatile("cp.async.bulk.shared::cluster.global.mbarrier::complete_tx::bytes [%0], [%1], %2, [%3];" \
                 :: "r"(dst), "l"(src), "r"((uint32_t)(bytes)), "r"(mbar) : "memory")

// mma.sync m16n8k16 fp16 -> fp32 accumulate
__device__ __forceinline__ void mma_f16(float* d, const uint32_t* a, const uint32_t* b) {
    asm("mma.sync.aligned.m16n8k16.row.col.f32.f16.f16.f32 "
        "{%0,%1,%2,%3}, {%4,%5,%6,%7}, {%8,%9}, {%0,%1,%2,%3};"
        : "+f"(d[0]), "+f"(d[1]), "+f"(d[2]), "+f"(d[3])
        : "r"(a[0]), "r"(a[1]), "r"(a[2]), "r"(a[3]), "r"(b[0]), "r"(b[1]));
}

// ---------------------------------------------------------------------------
// Fused prep (R7 structure).
// Blocks [0, 1024): E prep, 2 codes per block; B fragments in PAIRED order:
//   uint32 idx = (pass*4+ch)*4096 + ((ks*8 + (n_tile>>1))*32 + lane)*4
//                + (n_tile&1)*2 + reg
// Blocks [1024, 2048): X split, one (m_block, chunk) tile via two 16 KB smem
//   buffers (single phase), coalesced uint4 out. A-fragment order unchanged.
// ---------------------------------------------------------------------------
__global__ void __launch_bounds__(256) prep_all_kernel(const float* __restrict__ X,
                                                       const float* __restrict__ embed_sum,
                                                       const float* __restrict__ usage) {
    if (blockIdx.x < N_CODE / 2) {
        int t = threadIdx.x;
        int k = blockIdx.x * 2 + (t >> 7);
        int tl = t & 127;
        __shared__ float wsum[8];

        if (t < 32) g_key[blockIdx.x * 32 + t] = 0xFFFFFFFFFFFFFFFFull;

        float u = fmaxf(usage[k], 1e-5f);
        float2 vv = ((const float2*)embed_sum)[k * 128 + tl];
        float v0 = vv.x / u, v1 = vv.y / u;
        ((float2*)g_embed)[k * 128 + tl] = make_float2(v0, v1);

        __half h0 = __float2half_rn(v0);
        __half l0 = __float2half_rn(v0 - __half2float(h0));
        __half h1 = __float2half_rn(v1);
        __half l1 = __float2half_rn(v1 - __half2float(h1));

        int d = 2 * tl;
        int pass = k >> 7, n_in = k & 127;
        int n_tile = n_in >> 3, ncol = n_in & 7;
        int ch = d >> 6, kk = d & 63, ks = kk >> 4, kc = kk & 15;
        int lane = ncol * 4 + ((kc >> 1) & 3);
        int reg = kc >> 3;
        // paired order: two adjacent n_tiles share a 16-byte lane slot
        int u32i = (pass * 4 + ch) * 4096 +
                   ((ks * 8 + (n_tile >> 1)) * 32 + lane) * 4 +
                   (n_tile & 1) * 2 + reg;
        ((uint32_t*)g_ehi)[u32i] = pack2(h0, h1);
        ((uint32_t*)g_elo)[u32i] = pack2(l0, l1);

        float val = v0 * v0 + v1 * v1;
        #pragma unroll
        for (int off = 16; off > 0; off >>= 1)
            val += __shfl_down_sync(0xffffffffu, val, off);
        if ((t & 31) == 0) wsum[t >> 5] = val;
        __syncthreads();
        if (tl == 0) {
            int w0 = (t >> 7) * 4;
            g_esq[k] = wsum[w0] + wsum[w0 + 1] + wsum[w0 + 2] + wsum[w0 + 3];
        }
    } else {
        // -------- X split staged via smem, coalesced output (R7) -------------
        __shared__ uint32_t sh_hi[4096];   // 16 KB
        __shared__ uint32_t sh_lo[4096];   // 16 KB
        int tile = blockIdx.x - N_CODE / 2;     // 0..1023
        int m_block = tile >> 2, ch = tile & 3;
        int t = threadIdx.x;

        #pragma unroll
        for (int it = 0; it < 8; ++it) {
            int i4 = t + it * 256;                 // 0..2047 tile-local float4
            int tok_l = i4 >> 4;                   // 0..127
            int dl4 = i4 & 15;                     // float4 within 64-d chunk
            float4 x = ((const float4*)X)[(size_t)(m_block * 128 + tok_l) * 64 + ch * 16 + dl4];
            float xv[4] = {x.x, x.y, x.z, x.w};
            int m_tile = tok_l >> 4, r = tok_l & 15;
            #pragma unroll
            for (int j = 0; j < 4; j += 2) {
                __half ha = __float2half_rn(xv[j]);
                __half la = __float2half_rn(xv[j] - __half2float(ha));
                __half hb = __float2half_rn(xv[j + 1]);
                __half lb = __float2half_rn(xv[j + 1] - __half2float(hb));
                int kk = dl4 * 4 + j;              // 0..63 within chunk
                int ks = kk >> 4, kc = kk & 15;
                int lane = (r & 7) * 4 + ((kc >> 1) & 3);
                int reg = (r >> 3) | ((kc >> 3) << 1);
                int half_loc = ((ks * 8 + m_tile) * 32 + lane) * 8 + reg * 2;
                sh_hi[half_loc >> 1] = pack2(ha, hb);
                sh_lo[half_loc >> 1] = pack2(la, lb);
            }
        }
        __syncthreads();

        uint4* dh = (uint4*)(((uint32_t*)g_xhi) + tile * 4096);
        uint4* dl = (uint4*)(((uint32_t*)g_xlo) + tile * 4096);
        const uint4* sh4 = (const uint4*)sh_hi;
        const uint4* sl4 = (const uint4*)sh_lo;
        #pragma unroll
        for (int it = 0; it < 4; ++it) {
            dh[t + it * 256] = sh4[t + it * 256];
            dl[t + it * 256] = sl4[t + it * 256];
        }
    }
}

// ---------------------------------------------------------------------------
// Fused fp16x2 mma.sync GEMM + argmin (R12 structure, paired-B loads).
// Grid: 1024 CTAs = 256 m-tiles x 4 quarters. 288 threads = 8 compute + 1 prod.
// A (128 KB) persistent; B rings 3 x 32 KB. 4 passes x 128 codes, 4 chunks.
// ---------------------------------------------------------------------------
#define SMEM_TOTAL 232448
#define A_OFF 3072
#define B_OFF 134144

__global__ void __launch_bounds__(288, 1) argmin_mma_kernel() {
    extern __shared__ __align__(1024) char smem[];
    uint32_t sb = smem_u32(smem);
    int tid = threadIdx.x, lane = tid & 31, wid = tid >> 5;
    int mtile = blockIdx.x >> 2, q = blockIdx.x & 3;

    const uint32_t AF    = sb + 0;
    const uint32_t FB[3] = {sb + 8,  sb + 16, sb + 24};
    const uint32_t EB[3] = {sb + 32, sb + 40, sb + 48};
    float* esq_s = (float*)(smem + 1024);   // [512] quarter esq

    if (tid == 0) {
        MBAR_INIT(AF, 1);
        #pragma unroll
        for (int s = 0; s < 3; ++s) { MBAR_INIT(FB[s], 1); MBAR_INIT(EB[s], 8); }
    }
    for (int i = tid; i < 512; i += 288) esq_s[i] = g_esq[q * 512 + i];
    __syncthreads();

    int row0 = mtile * 128;

    if (wid == 8) {
        // ---------------- dedicated producer warp ---------------------------
        if (lane == 0) {
            MBAR_EXPECT_TX(AF, 131072);
            #pragma unroll
            for (int ch = 0; ch < 4; ++ch) {
                BULK_G2S(sb + A_OFF + ch * 32768,
                         &g_xhi[(mtile * 4 + ch) * 8192], 16384, AF);
                BULK_G2S(sb + A_OFF + ch * 32768 + 16384,
                         &g_xlo[(mtile * 4 + ch) * 8192], 16384, AF);
            }
            #pragma unroll 1
            for (int g = 0; g < 16; ++g) {
                int s = g % 3;
                if (g >= 3) MBAR_WAIT(EB[s], ((g / 3) + 1) & 1);
                int pass = g >> 2, ch = g & 3;
                uint32_t st = sb + B_OFF + s * 32768;
                MBAR_EXPECT_TX(FB[s], 32768);
                BULK_G2S(st,         &g_ehi[((q * 4 + pass) * 4 + ch) * 8192], 16384, FB[s]);
                BULK_G2S(st + 16384, &g_elo[((q * 4 + pass) * 4 + ch) * 8192], 16384, FB[s]);
            }
        }
    } else {
        // ---------------- 8 compute warps ------------------------------------
        int warp_m = wid & 3, warp_n = wid >> 2;
        int t4 = lane & 3, g4 = lane >> 2;

        float best[2][2];
        int bestI[2][2];
        #pragma unroll
        for (int a = 0; a < 2; ++a)
            #pragma unroll
            for (int b = 0; b < 2; ++b) { best[a][b] = 3.4e38f; bestI[a][b] = 0; }

        MBAR_WAIT(AF, 0);   // A resident for whole kernel

        #pragma unroll 1
        for (int pass = 0; pass < 4; ++pass) {
            float acc[2][8][4];
            #pragma unroll
            for (int mt = 0; mt < 2; ++mt)
                #pragma unroll
                for (int nt = 0; nt < 8; ++nt)
                    #pragma unroll
                    for (int j = 0; j < 4; ++j) acc[mt][nt][j] = 0.f;

            #pragma unroll 1
            for (int ch = 0; ch < 4; ++ch) {
                int g = pass * 4 + ch;
                int s = g % 3;
                MBAR_WAIT(FB[s], (g / 3) & 1);

                const char* Ah = smem + A_OFF + ch * 32768;
                const char* Al = Ah + 16384;
                const char* Bh = smem + B_OFF + s * 32768;
                const char* Bl = Bh + 16384;

                #pragma unroll
                for (int ks = 0; ks < 4; ++ks) {
                    uint32_t ah[2][4], al[2][4];
                    #pragma unroll
                    for (int mt = 0; mt < 2; ++mt) {
                        int off = ((ks * 8 + warp_m * 2 + mt) * 32 + lane) * 16;
                        *(uint4*)ah[mt] = *(const uint4*)(Ah + off);
                        *(uint4*)al[mt] = *(const uint4*)(Al + off);
                    }
                    // paired B loads: one uint4 covers two adjacent nt
                    uint32_t bh[8][2], bl[8][2];
                    #pragma unroll
                    for (int p = 0; p < 4; ++p) {
                        int off = ((ks * 8 + warp_n * 4 + p) * 32 + lane) * 16;
                        uint4 th = *(const uint4*)(Bh + off);
                        uint4 tl_ = *(const uint4*)(Bl + off);
                        bh[2 * p][0] = th.x; bh[2 * p][1] = th.y;
                        bh[2 * p + 1][0] = th.z; bh[2 * p + 1][1] = th.w;
                        bl[2 * p][0] = tl_.x; bl[2 * p][1] = tl_.y;
                        bl[2 * p + 1][0] = tl_.z; bl[2 * p + 1][1] = tl_.w;
                    }
                    // term-ordered: hi*hi, hi*lo, lo*hi
                    #pragma unroll
                    for (int mt = 0; mt < 2; ++mt)
                        #pragma unroll
                        for (int nt = 0; nt < 8; ++nt)
                            mma_f16(acc[mt][nt], ah[mt], bh[nt]);
                    #pragma unroll
                    for (int mt = 0; mt < 2; ++mt)
                        #pragma unroll
                        for (int nt = 0; nt < 8; ++nt)
                            mma_f16(acc[mt][nt], ah[mt], bl[nt]);
                    #pragma unroll
                    for (int mt = 0; mt < 2; ++mt)
                        #pragma unroll
                        for (int nt = 0; nt < 8; ++nt)
                            mma_f16(acc[mt][nt], al[mt], bh[nt]);
                }
                if (lane == 0) MBAR_ARRIVE(EB[s]);
            }

            // fold pass into running argmin: dist = esq - 2*dot
            #pragma unroll
            for (int nt = 0; nt < 8; ++nt) {
                int clocal = pass * 128 + warp_n * 64 + nt * 8 + 2 * t4;
                float e0 = esq_s[clocal], e1 = esq_s[clocal + 1];
                int cbase = q * 512 + clocal;
                #pragma unroll
                for (int mt = 0; mt < 2; ++mt) {
                    float d0v = fmaf(-2.f, acc[mt][nt][0], e0);
                    if (d0v < best[mt][0]) { best[mt][0] = d0v; bestI[mt][0] = cbase; }
                    float d1v = fmaf(-2.f, acc[mt][nt][1], e1);
                    if (d1v < best[mt][0]) { best[mt][0] = d1v; bestI[mt][0] = cbase + 1; }
                    float d2v = fmaf(-2.f, acc[mt][nt][2], e0);
                    if (d2v < best[mt][1]) { best[mt][1] = d2v; bestI[mt][1] = cbase; }
                    float d3v = fmaf(-2.f, acc[mt][nt][3], e1);
                    if (d3v < best[mt][1]) { best[mt][1] = d3v; bestI[mt][1] = cbase + 1; }
                }
            }
        }

        // width-4 shuffle reduce, then global atomic merge
        #pragma unroll
        for (int mt = 0; mt < 2; ++mt)
            #pragma unroll
            for (int h = 0; h < 2; ++h) {
                float b = best[mt][h];
                int bi = bestI[mt][h];
                #pragma unroll
                for (int off = 2; off > 0; off >>= 1) {
                    float ob = __shfl_down_sync(0xffffffffu, b, off, 4);
                    int obi = __shfl_down_sync(0xffffffffu, bi, off, 4);
                    if (ob < b || (ob == b && obi < bi)) { b = ob; bi = obi; }
                }
                if (t4 == 0) {
                    int tok = row0 + warp_m * 32 + mt * 16 + g4 + 8 * h;
                    unsigned long long key =
                        ((unsigned long long)fmono(b) << 32) | (uint32_t)bi;
                    atomicMin(&g_key[tok], key);
                }
            }
    }
}

// ---------------------------------------------------------------------------
// gather: one thread per (token, float4 chunk). 8192 CTAs x 256 threads.
// ---------------------------------------------------------------------------
__global__ void __launch_bounds__(256) gather_kernel(float* __restrict__ out, int N) {
    int i = blockIdx.x * 256 + threadIdx.x;     // [0, N*64)
    int tok = i >> 6, c4 = i & 63;
    int idx = (int)(g_key[tok] & 0xFFFFFFFFull);
    float4 v = ((const float4*)g_embed)[(size_t)idx * 64 + c4];
    ((float4*)out)[i] = v;
    if (c4 == 0) out[(size_t)N * D_DIM + tok] = (float)idx;
}

// ---------------------------------------------------------------------------
extern "C" void kernel_launch(void* const* d_in, const int* in_sizes, int n_in,
                              void* d_out, int out_size) {
    const float* X  = (const float*)d_in[0];
    const float* ES = (const float*)d_in[1];
    const float* U  = (const float*)d_in[2];
    float* out = (float*)d_out;
    (void)n_in; (void)out_size;
    int N = in_sizes[0] / D_DIM;   // 32768

    cudaFuncSetAttribute(argmin_mma_kernel,
                         cudaFuncAttributeMaxDynamicSharedMemorySize, SMEM_TOTAL);

    prep_all_kernel<<<N_CODE / 2 + (N / 128) * 4, 256>>>(X, ES, U);
    argmin_mma_kernel<<<(N / 128) * 4, 288, SMEM_TOTAL>>>();
    gather_kernel<<<(N * 64) / 256, 256>>>(out, N);
}